// round 9
// baseline (speedup 1.0000x reference)
#include <cuda_runtime.h>
#include <cuda_bf16.h>
#include <cuda_fp16.h>
#include <math.h>

#define F        128      // input features
#define HC       128      // H*C output features
#define NEG_SLOPE 0.2f
#define GN_EPS   1e-5f
#define LOG2E    1.4426950408889634f

#define MAX_N  50048
#define ELL_CAP 96        // max in-degree stored (Poisson(16): P(>96) ~ 0)

// ---- scratch (static device globals; no allocation allowed) ----
__device__ __half g_xl_h[MAX_N * F];        // x @ W_l  (fp16)
__device__ __half g_xr_h[MAX_N * F];        // x @ W_r  (fp16)
__device__ int    g_count[MAX_N];           // in-degree
__device__ int    g_ell[MAX_N * ELL_CAP];   // sources grouped by dst (ELL)
__device__ float  g_colsum[HC];
__device__ float  g_colsumsq[HC];
// pre-split, padded (LDAU=68) global images of [W_l|W_r]^T hi/lo bf16x2
__device__ unsigned g_bhi[256 * 68];
__device__ unsigned g_blo[256 * 68];

// ---------------------------------------------------------------
__global__ void init_kernel(int N) {
    int i = blockIdx.x * blockDim.x + threadIdx.x;
    if (i < N) g_count[i] = 0;
    if (i < HC) { g_colsum[i] = 0.f; g_colsumsq[i] = 0.f; }
}

__global__ void ell_kernel(const int* __restrict__ ei, int E) {
    int e = blockIdx.x * blockDim.x + threadIdx.x;
    if (e >= E) return;
    int src = __ldg(&ei[e]);
    int dst = __ldg(&ei[E + e]);
    int slot = atomicAdd(&g_count[dst], 1);
    if (slot < ELL_CAP) g_ell[(size_t)dst * ELL_CAP + slot] = src;
}

// ---------------------------------------------------------------
// split-bf16 tensor-core GEMM:  D[128,256] = X[128,128] @ [W_l | W_r]
// 3 mma terms: hi*hi + hi*lo + lo*hi  (fp32 acc; lo*lo ~2^-18, dropped)
// SMEM images padded to 136 bf16/row (272B stride -> conflict-free ldmatrix).
#define LDA 136
#define LDAU 68                      // uints per row
#define OFF_AHI 0
#define OFF_ALO 34816                // 128*136*2
#define OFF_BHI 69632
#define OFF_BLO 139264               // +256*136*2
#define SM_TOT  208896

__device__ __forceinline__ unsigned smem_u32(const void* p) {
    unsigned a;
    asm("{ .reg .u64 t; cvta.to.shared.u64 t, %1; cvt.u32.u64 %0, t; }"
        : "=r"(a) : "l"(p));
    return a;
}
__device__ __forceinline__ void ldm4(unsigned* r, unsigned addr) {
    asm volatile("ldmatrix.sync.aligned.m8n8.x4.shared.b16 {%0,%1,%2,%3}, [%4];"
                 : "=r"(r[0]), "=r"(r[1]), "=r"(r[2]), "=r"(r[3]) : "r"(addr));
}
__device__ __forceinline__ void mma16816(float* d, const unsigned* a,
                                         unsigned b0, unsigned b1) {
    asm volatile(
        "mma.sync.aligned.m16n8k16.row.col.f32.bf16.bf16.f32 "
        "{%0,%1,%2,%3}, {%4,%5,%6,%7}, {%8,%9}, {%0,%1,%2,%3};"
        : "+f"(d[0]), "+f"(d[1]), "+f"(d[2]), "+f"(d[3])
        : "r"(a[0]), "r"(a[1]), "r"(a[2]), "r"(a[3]), "r"(b0), "r"(b1));
}
__device__ __forceinline__ void split2(float f0, float f1,
                                       unsigned& hi, unsigned& lo) {
    __nv_bfloat16 h0 = __float2bfloat16_rn(f0);
    __nv_bfloat16 h1 = __float2bfloat16_rn(f1);
    hi = ((unsigned)__bfloat16_as_ushort(h1) << 16) |
          (unsigned)__bfloat16_as_ushort(h0);
    float l0 = f0 - __bfloat162float(h0);
    float l1 = f1 - __bfloat162float(h1);
    asm("cvt.rn.bf16x2.f32 %0, %1, %2;" : "=r"(lo) : "f"(l1), "f"(l0));
}

// one-time-per-call W prep: split + transpose into padded global image
__global__ void prep_w_kernel(const float* __restrict__ Wl,
                              const float* __restrict__ Wr) {
    int p = blockIdx.x * blockDim.x + threadIdx.x;   // 0..16383
    if (p >= 16384) return;
    int n  = p >> 6;           // 0..255 combined output feature
    int kp = p & 63;           // k-pair
    const float* W = (n < 128) ? Wl : Wr;
    int nn = n & 127;
    float f0 = __ldg(&W[(size_t)(2 * kp) * 128 + nn]);
    float f1 = __ldg(&W[(size_t)(2 * kp + 1) * 128 + nn]);
    unsigned h, l;
    split2(f0, f1, h, l);
    g_bhi[n * LDAU + kp] = h;
    g_blo[n * LDAU + kp] = l;
}

__global__ __launch_bounds__(256) void mma_gemm_kernel(
    const float* __restrict__ X, int N)
{
    extern __shared__ char smem[];
    unsigned sb = smem_u32(smem);
    const int tid    = threadIdx.x;
    const int lane   = tid & 31;
    const int wid    = tid >> 5;
    const int warp_m = wid >> 1;          // 0..3 -> rows warp_m*32
    const int warp_n = wid & 1;           // 0..1 -> cols warp_n*64 (per half)
    const int row0   = blockIdx.x * 128;

    // ---- fill B: flat uint4 copy of pre-split global images ----
    // unroll 1 is load-bearing: full unroll front-batches 34 uint4 loads
    // (136 regs), spilling the accumulator tile (R8 regression).
    {
        const uint4* bh = (const uint4*)g_bhi;   // 4352 uint4
        const uint4* bl = (const uint4*)g_blo;
        uint4* dh = (uint4*)(smem + OFF_BHI);
        uint4* dl = (uint4*)(smem + OFF_BLO);
        #pragma unroll 1
        for (int i = tid; i < 4352; i += 256) {
            dh[i] = __ldg(&bh[i]);
            dl[i] = __ldg(&bl[i]);
        }
    }
    // ---- fill A (split X rows) ----
    {
        int r = tid >> 1;
        int kb = (tid & 1) * 64;
        unsigned* ah = (unsigned*)(smem + OFF_AHI) + r * LDAU + (kb >> 1);
        unsigned* al = (unsigned*)(smem + OFF_ALO) + r * LDAU + (kb >> 1);
        int grow = row0 + r;
        if (grow < N) {
            const float4* xp = (const float4*)&X[(size_t)grow * F + kb];
            #pragma unroll 4
            for (int j = 0; j < 16; j++) {
                float4 v = __ldg(&xp[j]);
                unsigned h0, l0, h1, l1;
                split2(v.x, v.y, h0, l0);
                split2(v.z, v.w, h1, l1);
                ah[j * 2] = h0; ah[j * 2 + 1] = h1;
                al[j * 2] = l0; al[j * 2 + 1] = l1;
            }
        } else {
            #pragma unroll
            for (int j = 0; j < 32; j++) { ah[j] = 0u; al[j] = 0u; }
        }
    }
    __syncthreads();

    // per-lane ldmatrix address components (bytes)
    const unsigned aoff = (unsigned)(warp_m * 32 + (lane & 15)) * (LDA * 2) +
                          ((unsigned)(lane >> 4) << 4);
    const unsigned boff = (unsigned)((lane & 7) + ((lane >> 4) << 3)) * (LDA * 2) +
                          ((unsigned)((lane >> 3) & 1) << 4);

    #pragma unroll
    for (int h = 0; h < 2; h++) {
        float acc[2][8][4];
        #pragma unroll
        for (int mt = 0; mt < 2; mt++)
            #pragma unroll
            for (int nt = 0; nt < 8; nt++)
                #pragma unroll
                for (int q = 0; q < 4; q++) acc[mt][nt][q] = 0.f;

        const unsigned nbase = (unsigned)(h * 128 + warp_n * 64) * (LDA * 2);

        #pragma unroll
        for (int term = 0; term < 3; term++) {
            const unsigned Ab = sb + ((term < 2) ? OFF_AHI : OFF_ALO) + aoff;
            const unsigned Bb = sb + ((term == 1) ? OFF_BLO : OFF_BHI) + nbase + boff;
            #pragma unroll
            for (int ks = 0; ks < 8; ks++) {
                const unsigned kb = (unsigned)ks * 32;   // k0*2 bytes
                unsigned a0[4], a1[4];
                ldm4(a0, Ab + kb);
                ldm4(a1, Ab + 16 * (LDA * 2) + kb);
                unsigned b[4][4];
                #pragma unroll
                for (int p = 0; p < 4; p++)
                    ldm4(b[p], Bb + (unsigned)p * 16 * (LDA * 2) + kb);
                #pragma unroll
                for (int mt = 0; mt < 2; mt++) {
                    const unsigned* aa = mt ? a1 : a0;
                    #pragma unroll
                    for (int nt = 0; nt < 8; nt++)
                        mma16816(acc[mt][nt], aa,
                                 b[nt >> 1][(nt & 1) * 2],
                                 b[nt >> 1][(nt & 1) * 2 + 1]);
                }
            }
        }
        // store this half as fp16
        __half* dst = h ? g_xr_h : g_xl_h;
        #pragma unroll
        for (int mt = 0; mt < 2; mt++) {
            int row = row0 + warp_m * 32 + mt * 16 + (lane >> 2);
            #pragma unroll
            for (int nt = 0; nt < 8; nt++) {
                int col = warp_n * 64 + nt * 8 + (lane & 3) * 2;
                if (row < N)
                    *(__half2*)&dst[(size_t)row * HC + col] =
                        __floats2half2_rn(acc[mt][nt][0], acc[mt][nt][1]);
                if (row + 8 < N)
                    *(__half2*)&dst[(size_t)(row + 8) * HC + col] =
                        __floats2half2_rn(acc[mt][nt][2], acc[mt][nt][3]);
            }
        }
    }
}

// ---------------------------------------------------------------
// FUSED attention + column stats.  Warp per dst node, 2 edges at a time:
// lanes 0-15 process edge i, lanes 16-31 edge i+1; 8 channels per lane.
__global__ __launch_bounds__(256) void fused_attn_kernel(
    const float* __restrict__ att, const float* __restrict__ bias,
    float* __restrict__ out, int N)
{
    __shared__ float bsum[HC];
    __shared__ float bssq[HC];
    const int tid = threadIdx.x;
    if (tid < HC) { bsum[tid] = 0.f; bssq[tid] = 0.f; }
    __syncthreads();

    const int node = blockIdx.x * 8 + (tid >> 5);
    if (node < N) {
        const int lane = tid & 31;
        const int half = lane >> 4;          // edge slot within pair
        const int sl   = lane & 15;          // sublane: channels sl*8..sl*8+7
        const int c8   = sl * 8;

        // att (pre-scaled by log2e) and x_r row for my 8 channels
        float a[8], r[8];
        {
            float4 t0 = *(const float4*)&att[c8];
            float4 t1 = *(const float4*)&att[c8 + 4];
            a[0]=t0.x*LOG2E; a[1]=t0.y*LOG2E; a[2]=t0.z*LOG2E; a[3]=t0.w*LOG2E;
            a[4]=t1.x*LOG2E; a[5]=t1.y*LOG2E; a[6]=t1.z*LOG2E; a[7]=t1.w*LOG2E;
            uint4 u = *(const uint4*)&g_xr_h[(size_t)node * HC + c8];
            float2 f0 = __half22float2(*(__half2*)&u.x);
            float2 f1 = __half22float2(*(__half2*)&u.y);
            float2 f2 = __half22float2(*(__half2*)&u.z);
            float2 f3 = __half22float2(*(__half2*)&u.w);
            r[0]=f0.x; r[1]=f0.y; r[2]=f1.x; r[3]=f1.y;
            r[4]=f2.x; r[5]=f2.y; r[6]=f3.x; r[7]=f3.y;
        }

        float denom = 0.f;
        float acc[8];
        #pragma unroll
        for (int j = 0; j < 8; j++) acc[j] = 0.f;

        const int cnt = min(g_count[node], ELL_CAP);
        const int* lst = &g_ell[(size_t)node * ELL_CAP];

#define EDGE(ROW, M) {                                               \
            uint4 u = *(const uint4*)&g_xl_h[(size_t)(ROW) * HC + c8]; \
            float2 f0 = __half22float2(*(__half2*)&u.x);             \
            float2 f1 = __half22float2(*(__half2*)&u.y);             \
            float2 f2 = __half22float2(*(__half2*)&u.z);             \
            float2 f3 = __half22float2(*(__half2*)&u.w);             \
            float l[8] = {f0.x, f0.y, f1.x, f1.y, f2.x, f2.y, f3.x, f3.y}; \
            float s = 0.f;                                           \
            _Pragma("unroll")                                        \
            for (int j = 0; j < 8; j++) {                            \
                float e = l[j] + r[j];                               \
                e = fmaxf(e, NEG_SLOPE * e);                         \
                s = fmaf(a[j], e, s);                                \
            }                                                        \
            s += __shfl_xor_sync(0xffffffffu, s, 1);                 \
            s += __shfl_xor_sync(0xffffffffu, s, 2);                 \
            float we = exp2f(s) * (M);                               \
            denom += we;                                             \
            _Pragma("unroll")                                        \
            for (int j = 0; j < 8; j++) acc[j] = fmaf(we, l[j], acc[j]); }

        // self loop: only half 0 contributes
        EDGE(node, half ? 0.f : 1.f);

        int i = 0;
        for (; i + 4 <= cnt; i += 4) {       // 2 pairs per iter, no masks
            int s0 = __ldg(&lst[i + half]);
            int s1 = __ldg(&lst[i + 2 + half]);
            EDGE(s0, 1.f);
            EDGE(s1, 1.f);
        }
        for (; i < cnt; i += 2) {            // masked tail pair
            int slot = i + half;
            float m = (slot < cnt) ? 1.f : 0.f;
            int s0 = __ldg(&lst[slot < cnt ? slot : 0]);
            EDGE(s0, m);
        }
#undef EDGE

        // combine the two half-warps
        denom += __shfl_xor_sync(0xffffffffu, denom, 16);
        #pragma unroll
        for (int j = 0; j < 8; j++)
            acc[j] += __shfl_xor_sync(0xffffffffu, acc[j], 16);

        if (half == 0) {
            float inv = 1.f / denom;
            float4 b0 = *(const float4*)&bias[c8];
            float4 b1 = *(const float4*)&bias[c8 + 4];
            float o[8];
            o[0]=fmaf(acc[0],inv,b0.x); o[1]=fmaf(acc[1],inv,b0.y);
            o[2]=fmaf(acc[2],inv,b0.z); o[3]=fmaf(acc[3],inv,b0.w);
            o[4]=fmaf(acc[4],inv,b1.x); o[5]=fmaf(acc[5],inv,b1.y);
            o[6]=fmaf(acc[6],inv,b1.z); o[7]=fmaf(acc[7],inv,b1.w);
            *(float4*)&out[(size_t)node * HC + c8] =
                make_float4(o[0], o[1], o[2], o[3]);
            *(float4*)&out[(size_t)node * HC + c8 + 4] =
                make_float4(o[4], o[5], o[6], o[7]);
            #pragma unroll
            for (int j = 0; j < 8; j++) {
                atomicAdd(&bsum[c8 + j], o[j]);
                atomicAdd(&bssq[c8 + j], o[j] * o[j]);
            }
        }
    }
    __syncthreads();
    if (tid < HC) {
        atomicAdd(&g_colsum[tid], bsum[tid]);
        atomicAdd(&g_colsumsq[tid], bssq[tid]);
    }
}

// ---------------------------------------------------------------
__global__ void norm_kernel(float* __restrict__ out,
                            const float* __restrict__ gw,
                            const float* __restrict__ gb,
                            const float* __restrict__ gms, int N)
{
    int i = blockIdx.x * blockDim.x + threadIdx.x;
    if (i >= N * HC) return;
    int f = i & (HC - 1);
    float invN = 1.f / (float)N;
    float m  = g_colsum[f] * invN;
    float m2 = g_colsumsq[f] * invN;
    float s  = gms[f];
    float var = m2 - s * (2.f - s) * m * m;
    float v = out[i];
    out[i] = gw[f] * (v - s * m) * rsqrtf(var + GN_EPS) + gb[f];
}

// ---------------------------------------------------------------
extern "C" void kernel_launch(void* const* d_in, const int* in_sizes, int n_in,
                              void* d_out, int out_size)
{
    const float* x    = (const float*)d_in[0];
    const int*   ei   = (const int*)  d_in[1];
    const float* W_l  = (const float*)d_in[2];
    const float* W_r  = (const float*)d_in[3];
    const float* att  = (const float*)d_in[4];
    const float* bias = (const float*)d_in[5];
    const float* gw   = (const float*)d_in[6];
    const float* gb   = (const float*)d_in[7];
    const float* gms  = (const float*)d_in[8];
    float* out = (float*)d_out;

    const int N = in_sizes[0] / F;
    const int E = in_sizes[1] / 2;

    static int smem_set = 0;
    if (!smem_set) {
        cudaFuncSetAttribute(mma_gemm_kernel,
                             cudaFuncAttributeMaxDynamicSharedMemorySize, SM_TOT);
        smem_set = 1;
    }

    // adjacency (ELL) build + weight prep (independent of each other)
    init_kernel<<<(N + 255) / 256, 256>>>(N);
    prep_w_kernel<<<64, 256>>>(W_l, W_r);
    ell_kernel<<<(E + 255) / 256, 256>>>(ei, E);

    // projections (tensor-core, split-bf16, both outputs in one pass)
    mma_gemm_kernel<<<(N + 127) / 128, 256, SM_TOT>>>(x, N);

    // fused attention (softmax + aggregation + column stats)
    fused_attn_kernel<<<(N + 7) / 8, 256>>>(att, bias, out, N);

    // GraphNorm
    norm_kernel<<<(N * HC + 255) / 256, 256>>>(out, gw, gb, gms, N);
}

// round 12
// speedup vs baseline: 1.4288x; 1.4288x over previous
#include <cuda_runtime.h>
#include <cuda_bf16.h>
#include <cuda_fp16.h>
#include <math.h>

#define F        128      // input features
#define HC       128      // H*C output features
#define NEG_SLOPE 0.2f
#define GN_EPS   1e-5f
#define LOG2E    1.4426950408889634f

#define MAX_N  50048
#define ELL_CAP 96        // max in-degree stored (Poisson(16): P(>96) ~ 0)

// ---- scratch (static device globals; no allocation allowed) ----
__device__ __half g_xl_h[MAX_N * F];        // x @ W_l  (fp16)
__device__ __half g_xr_h[MAX_N * F];        // x @ W_r  (fp16)
__device__ int    g_count[MAX_N];           // in-degree
__device__ int    g_ell[MAX_N * ELL_CAP];   // sources grouped by dst (ELL)
__device__ float  g_colsum[HC];
__device__ float  g_colsumsq[HC];

// ---------------------------------------------------------------
__global__ void init_kernel(int N) {
    int i = blockIdx.x * blockDim.x + threadIdx.x;
    if (i < N) g_count[i] = 0;
    if (i < HC) { g_colsum[i] = 0.f; g_colsumsq[i] = 0.f; }
}

__global__ void ell_kernel(const int* __restrict__ ei, int E) {
    int e = blockIdx.x * blockDim.x + threadIdx.x;
    if (e >= E) return;
    int src = __ldg(&ei[e]);
    int dst = __ldg(&ei[E + e]);
    int slot = atomicAdd(&g_count[dst], 1);
    if (slot < ELL_CAP) g_ell[(size_t)dst * ELL_CAP + slot] = src;
}

// ---------------------------------------------------------------
// split-bf16 tensor-core GEMM:  D[128,256] = X[128,128] @ [W_l | W_r]
// 3 mma terms: hi*hi + hi*lo + lo*hi  (fp32 acc; lo*lo ~2^-18, dropped)
// SMEM images padded to 136 bf16/row (272B stride -> conflict-free ldmatrix).
// (exact R7 configuration — measured best at 143.8us total)
#define LDA 136
#define LDAU 68                      // uints per row
#define OFF_AHI 0
#define OFF_ALO 34816                // 128*136*2
#define OFF_BHI 69632
#define OFF_BLO 139264               // +256*136*2
#define SM_TOT  208896

__device__ __forceinline__ unsigned smem_u32(const void* p) {
    unsigned a;
    asm("{ .reg .u64 t; cvta.to.shared.u64 t, %1; cvt.u32.u64 %0, t; }"
        : "=r"(a) : "l"(p));
    return a;
}
__device__ __forceinline__ void ldm4(unsigned* r, unsigned addr) {
    asm volatile("ldmatrix.sync.aligned.m8n8.x4.shared.b16 {%0,%1,%2,%3}, [%4];"
                 : "=r"(r[0]), "=r"(r[1]), "=r"(r[2]), "=r"(r[3]) : "r"(addr));
}
__device__ __forceinline__ void mma16816(float* d, const unsigned* a,
                                         unsigned b0, unsigned b1) {
    asm volatile(
        "mma.sync.aligned.m16n8k16.row.col.f32.bf16.bf16.f32 "
        "{%0,%1,%2,%3}, {%4,%5,%6,%7}, {%8,%9}, {%0,%1,%2,%3};"
        : "+f"(d[0]), "+f"(d[1]), "+f"(d[2]), "+f"(d[3])
        : "r"(a[0]), "r"(a[1]), "r"(a[2]), "r"(a[3]), "r"(b0), "r"(b1));
}
__device__ __forceinline__ void split2(float f0, float f1,
                                       unsigned& hi, unsigned& lo) {
    __nv_bfloat16 h0 = __float2bfloat16_rn(f0);
    __nv_bfloat16 h1 = __float2bfloat16_rn(f1);
    hi = ((unsigned)__bfloat16_as_ushort(h1) << 16) |
          (unsigned)__bfloat16_as_ushort(h0);
    float l0 = f0 - __bfloat162float(h0);
    float l1 = f1 - __bfloat162float(h1);
    asm("cvt.rn.bf16x2.f32 %0, %1, %2;" : "=r"(lo) : "f"(l1), "f"(l0));
}

__global__ __launch_bounds__(256) void mma_gemm_kernel(
    const float* __restrict__ X, const float* __restrict__ Wl,
    const float* __restrict__ Wr, int N)
{
    extern __shared__ char smem[];
    unsigned sb = smem_u32(smem);
    const int tid    = threadIdx.x;
    const int lane   = tid & 31;
    const int wid    = tid >> 5;
    const int warp_m = wid >> 1;          // 0..3 -> rows warp_m*32
    const int warp_n = wid & 1;           // 0..1 -> cols warp_n*64 (per half)
    const int row0   = blockIdx.x * 128;

    // ---- fill A (split X rows) ----
    {
        int r = tid >> 1;
        int kb = (tid & 1) * 64;
        unsigned* ah = (unsigned*)(smem + OFF_AHI) + r * LDAU + (kb >> 1);
        unsigned* al = (unsigned*)(smem + OFF_ALO) + r * LDAU + (kb >> 1);
        int grow = row0 + r;
        if (grow < N) {
            const float4* xp = (const float4*)&X[(size_t)grow * F + kb];
            #pragma unroll
            for (int j = 0; j < 16; j++) {
                float4 v = __ldg(&xp[j]);
                unsigned h0, l0, h1, l1;
                split2(v.x, v.y, h0, l0);
                split2(v.z, v.w, h1, l1);
                ah[j * 2] = h0; ah[j * 2 + 1] = h1;
                al[j * 2] = l0; al[j * 2 + 1] = l1;
            }
        } else {
            #pragma unroll
            for (int j = 0; j < 32; j++) { ah[j] = 0u; al[j] = 0u; }
        }
    }
    // ---- fill B transposed (Bt[n][k] = W[k][n]), split ----
    {
        int n = tid;                       // 0..255
        const float* W = (n < 128) ? Wl : Wr;
        int nn = n & 127;
        unsigned* bh = (unsigned*)(smem + OFF_BHI) + n * LDAU;
        unsigned* bl = (unsigned*)(smem + OFF_BLO) + n * LDAU;
        #pragma unroll 8
        for (int k = 0; k < 128; k += 2) {
            float f0 = __ldg(&W[(size_t)k * 128 + nn]);
            float f1 = __ldg(&W[(size_t)(k + 1) * 128 + nn]);
            unsigned h, l;
            split2(f0, f1, h, l);
            bh[k >> 1] = h; bl[k >> 1] = l;
        }
    }
    __syncthreads();

    // per-lane ldmatrix address components (bytes)
    const unsigned aoff = (unsigned)(warp_m * 32 + (lane & 15)) * (LDA * 2) +
                          ((unsigned)(lane >> 4) << 4);
    const unsigned boff = (unsigned)((lane & 7) + ((lane >> 4) << 3)) * (LDA * 2) +
                          ((unsigned)((lane >> 3) & 1) << 4);

    #pragma unroll
    for (int h = 0; h < 2; h++) {
        float acc[2][8][4];
        #pragma unroll
        for (int mt = 0; mt < 2; mt++)
            #pragma unroll
            for (int nt = 0; nt < 8; nt++)
                #pragma unroll
                for (int q = 0; q < 4; q++) acc[mt][nt][q] = 0.f;

        const unsigned nbase = (unsigned)(h * 128 + warp_n * 64) * (LDA * 2);

        #pragma unroll
        for (int term = 0; term < 3; term++) {
            const unsigned Ab = sb + ((term < 2) ? OFF_AHI : OFF_ALO) + aoff;
            const unsigned Bb = sb + ((term == 1) ? OFF_BLO : OFF_BHI) + nbase + boff;
            #pragma unroll
            for (int ks = 0; ks < 8; ks++) {
                const unsigned kb = (unsigned)ks * 32;   // k0*2 bytes
                unsigned a0[4], a1[4];
                ldm4(a0, Ab + kb);
                ldm4(a1, Ab + 16 * (LDA * 2) + kb);
                unsigned b[4][4];
                #pragma unroll
                for (int p = 0; p < 4; p++)
                    ldm4(b[p], Bb + (unsigned)p * 16 * (LDA * 2) + kb);
                #pragma unroll
                for (int mt = 0; mt < 2; mt++) {
                    const unsigned* aa = mt ? a1 : a0;
                    #pragma unroll
                    for (int nt = 0; nt < 8; nt++)
                        mma16816(acc[mt][nt], aa,
                                 b[nt >> 1][(nt & 1) * 2],
                                 b[nt >> 1][(nt & 1) * 2 + 1]);
                }
            }
        }
        // store this half as fp16
        __half* dst = h ? g_xr_h : g_xl_h;
        #pragma unroll
        for (int mt = 0; mt < 2; mt++) {
            int row = row0 + warp_m * 32 + mt * 16 + (lane >> 2);
            #pragma unroll
            for (int nt = 0; nt < 8; nt++) {
                int col = warp_n * 64 + nt * 8 + (lane & 3) * 2;
                if (row < N)
                    *(__half2*)&dst[(size_t)row * HC + col] =
                        __floats2half2_rn(acc[mt][nt][0], acc[mt][nt][1]);
                if (row + 8 < N)
                    *(__half2*)&dst[(size_t)(row + 8) * HC + col] =
                        __floats2half2_rn(acc[mt][nt][2], acc[mt][nt][3]);
            }
        }
    }
}

// ---------------------------------------------------------------
// FUSED attention + column stats.  Warp per dst node, 2 edges at a time:
// lanes 0-15 process edge i, lanes 16-31 edge i+1; 8 channels per lane.
__global__ __launch_bounds__(256) void fused_attn_kernel(
    const float* __restrict__ att, const float* __restrict__ bias,
    float* __restrict__ out, int N)
{
    __shared__ float bsum[HC];
    __shared__ float bssq[HC];
    const int tid = threadIdx.x;
    if (tid < HC) { bsum[tid] = 0.f; bssq[tid] = 0.f; }
    __syncthreads();

    const int node = blockIdx.x * 8 + (tid >> 5);
    if (node < N) {
        const int lane = tid & 31;
        const int half = lane >> 4;          // edge slot within pair
        const int sl   = lane & 15;          // sublane: channels sl*8..sl*8+7
        const int c8   = sl * 8;

        // att (pre-scaled by log2e) and x_r row for my 8 channels
        float a[8], r[8];
        {
            float4 t0 = *(const float4*)&att[c8];
            float4 t1 = *(const float4*)&att[c8 + 4];
            a[0]=t0.x*LOG2E; a[1]=t0.y*LOG2E; a[2]=t0.z*LOG2E; a[3]=t0.w*LOG2E;
            a[4]=t1.x*LOG2E; a[5]=t1.y*LOG2E; a[6]=t1.z*LOG2E; a[7]=t1.w*LOG2E;
            uint4 u = *(const uint4*)&g_xr_h[(size_t)node * HC + c8];
            float2 f0 = __half22float2(*(__half2*)&u.x);
            float2 f1 = __half22float2(*(__half2*)&u.y);
            float2 f2 = __half22float2(*(__half2*)&u.z);
            float2 f3 = __half22float2(*(__half2*)&u.w);
            r[0]=f0.x; r[1]=f0.y; r[2]=f1.x; r[3]=f1.y;
            r[4]=f2.x; r[5]=f2.y; r[6]=f3.x; r[7]=f3.y;
        }

        float denom = 0.f;
        float acc[8];
        #pragma unroll
        for (int j = 0; j < 8; j++) acc[j] = 0.f;

        const int cnt = min(g_count[node], ELL_CAP);
        const int* lst = &g_ell[(size_t)node * ELL_CAP];

#define EDGE(ROW, M) {                                               \
            uint4 u = *(const uint4*)&g_xl_h[(size_t)(ROW) * HC + c8]; \
            float2 f0 = __half22float2(*(__half2*)&u.x);             \
            float2 f1 = __half22float2(*(__half2*)&u.y);             \
            float2 f2 = __half22float2(*(__half2*)&u.z);             \
            float2 f3 = __half22float2(*(__half2*)&u.w);             \
            float l[8] = {f0.x, f0.y, f1.x, f1.y, f2.x, f2.y, f3.x, f3.y}; \
            float s = 0.f;                                           \
            _Pragma("unroll")                                        \
            for (int j = 0; j < 8; j++) {                            \
                float e = l[j] + r[j];                               \
                e = fmaxf(e, NEG_SLOPE * e);                         \
                s = fmaf(a[j], e, s);                                \
            }                                                        \
            s += __shfl_xor_sync(0xffffffffu, s, 1);                 \
            s += __shfl_xor_sync(0xffffffffu, s, 2);                 \
            float we = exp2f(s) * (M);                               \
            denom += we;                                             \
            _Pragma("unroll")                                        \
            for (int j = 0; j < 8; j++) acc[j] = fmaf(we, l[j], acc[j]); }

        // self loop: only half 0 contributes
        EDGE(node, half ? 0.f : 1.f);

        int i = 0;
        for (; i + 4 <= cnt; i += 4) {       // 2 pairs per iter, no masks
            int s0 = __ldg(&lst[i + half]);
            int s1 = __ldg(&lst[i + 2 + half]);
            EDGE(s0, 1.f);
            EDGE(s1, 1.f);
        }
        for (; i < cnt; i += 2) {            // masked tail pair
            int slot = i + half;
            float m = (slot < cnt) ? 1.f : 0.f;
            int s0 = __ldg(&lst[slot < cnt ? slot : 0]);
            EDGE(s0, m);
        }
#undef EDGE

        // combine the two half-warps
        denom += __shfl_xor_sync(0xffffffffu, denom, 16);
        #pragma unroll
        for (int j = 0; j < 8; j++)
            acc[j] += __shfl_xor_sync(0xffffffffu, acc[j], 16);

        if (half == 0) {
            float inv = 1.f / denom;
            float4 b0 = *(const float4*)&bias[c8];
            float4 b1 = *(const float4*)&bias[c8 + 4];
            float o[8];
            o[0]=fmaf(acc[0],inv,b0.x); o[1]=fmaf(acc[1],inv,b0.y);
            o[2]=fmaf(acc[2],inv,b0.z); o[3]=fmaf(acc[3],inv,b0.w);
            o[4]=fmaf(acc[4],inv,b1.x); o[5]=fmaf(acc[5],inv,b1.y);
            o[6]=fmaf(acc[6],inv,b1.z); o[7]=fmaf(acc[7],inv,b1.w);
            *(float4*)&out[(size_t)node * HC + c8] =
                make_float4(o[0], o[1], o[2], o[3]);
            *(float4*)&out[(size_t)node * HC + c8 + 4] =
                make_float4(o[4], o[5], o[6], o[7]);
            #pragma unroll
            for (int j = 0; j < 8; j++) {
                atomicAdd(&bsum[c8 + j], o[j]);
                atomicAdd(&bssq[c8 + j], o[j] * o[j]);
            }
        }
    }
    __syncthreads();
    if (tid < HC) {
        atomicAdd(&g_colsum[tid], bsum[tid]);
        atomicAdd(&g_colsumsq[tid], bssq[tid]);
    }
}

// ---------------------------------------------------------------
__global__ void norm_kernel(float* __restrict__ out,
                            const float* __restrict__ gw,
                            const float* __restrict__ gb,
                            const float* __restrict__ gms, int N)
{
    int i = blockIdx.x * blockDim.x + threadIdx.x;
    if (i >= N * HC) return;
    int f = i & (HC - 1);
    float invN = 1.f / (float)N;
    float m  = g_colsum[f] * invN;
    float m2 = g_colsumsq[f] * invN;
    float s  = gms[f];
    float var = m2 - s * (2.f - s) * m * m;
    float v = out[i];
    out[i] = gw[f] * (v - s * m) * rsqrtf(var + GN_EPS) + gb[f];
}

// ---------------------------------------------------------------
extern "C" void kernel_launch(void* const* d_in, const int* in_sizes, int n_in,
                              void* d_out, int out_size)
{
    const float* x    = (const float*)d_in[0];
    const int*   ei   = (const int*)  d_in[1];
    const float* W_l  = (const float*)d_in[2];
    const float* W_r  = (const float*)d_in[3];
    const float* att  = (const float*)d_in[4];
    const float* bias = (const float*)d_in[5];
    const float* gw   = (const float*)d_in[6];
    const float* gb   = (const float*)d_in[7];
    const float* gms  = (const float*)d_in[8];
    float* out = (float*)d_out;

    const int N = in_sizes[0] / F;
    const int E = in_sizes[1] / 2;

    static int smem_set = 0;
    if (!smem_set) {
        cudaFuncSetAttribute(mma_gemm_kernel,
                             cudaFuncAttributeMaxDynamicSharedMemorySize, SM_TOT);
        smem_set = 1;
    }

    // adjacency (ELL) build
    init_kernel<<<(N + 255) / 256, 256>>>(N);
    ell_kernel<<<(E + 255) / 256, 256>>>(ei, E);

    // projections (tensor-core, split-bf16, both outputs in one pass)
    mma_gemm_kernel<<<(N + 127) / 128, 256, SM_TOT>>>(x, W_l, W_r, N);

    // fused attention (softmax + aggregation + column stats)
    fused_attn_kernel<<<(N + 7) / 8, 256>>>(att, bias, out, N);

    // GraphNorm
    norm_kernel<<<(N * HC + 255) / 256, 256>>>(out, gw, gb, gms, N);
}

// round 13
// speedup vs baseline: 1.6552x; 1.1584x over previous
#include <cuda_runtime.h>
#include <cuda_bf16.h>
#include <cuda_fp16.h>
#include <math.h>

#define F        128      // input features
#define HC       128      // H*C output features
#define NEG_SLOPE 0.2f
#define GN_EPS   1e-5f
#define LOG2E    1.4426950408889634f

#define MAX_N  50048
#define ELL_CAP 96        // max in-degree stored (Poisson(16): P(>96) ~ 0)

// ---- scratch (static device globals; no allocation allowed) ----
__device__ __half g_xl_h[MAX_N * F];        // x @ W_l  (fp16)
__device__ __half g_xr_h[MAX_N * F];        // x @ W_r  (fp16)
__device__ int    g_count[MAX_N];           // in-degree
__device__ int    g_ell[MAX_N * ELL_CAP];   // sources grouped by dst (ELL)
__device__ float  g_colsum[HC];
__device__ float  g_colsumsq[HC];

// ---------------------------------------------------------------
__global__ void init_kernel(int N) {
    int i = blockIdx.x * blockDim.x + threadIdx.x;
    if (i < N) g_count[i] = 0;
    if (i < HC) { g_colsum[i] = 0.f; g_colsumsq[i] = 0.f; }
}

__global__ void ell_kernel(const int* __restrict__ ei, int E) {
    int e = blockIdx.x * blockDim.x + threadIdx.x;
    if (e >= E) return;
    int src = __ldg(&ei[e]);
    int dst = __ldg(&ei[E + e]);
    int slot = atomicAdd(&g_count[dst], 1);
    if (slot < ELL_CAP) g_ell[(size_t)dst * ELL_CAP + slot] = src;
}

// ---------------------------------------------------------------
// split-bf16 tensor-core GEMM:  D[128,256] = X[128,128] @ [W_l | W_r]
// (exact R7 configuration — measured good)
#define LDA 136
#define LDAU 68                      // uints per row
#define OFF_AHI 0
#define OFF_ALO 34816                // 128*136*2
#define OFF_BHI 69632
#define OFF_BLO 139264               // +256*136*2
#define SM_TOT  208896

__device__ __forceinline__ unsigned smem_u32(const void* p) {
    unsigned a;
    asm("{ .reg .u64 t; cvta.to.shared.u64 t, %1; cvt.u32.u64 %0, t; }"
        : "=r"(a) : "l"(p));
    return a;
}
__device__ __forceinline__ void ldm4(unsigned* r, unsigned addr) {
    asm volatile("ldmatrix.sync.aligned.m8n8.x4.shared.b16 {%0,%1,%2,%3}, [%4];"
                 : "=r"(r[0]), "=r"(r[1]), "=r"(r[2]), "=r"(r[3]) : "r"(addr));
}
__device__ __forceinline__ void mma16816(float* d, const unsigned* a,
                                         unsigned b0, unsigned b1) {
    asm volatile(
        "mma.sync.aligned.m16n8k16.row.col.f32.bf16.bf16.f32 "
        "{%0,%1,%2,%3}, {%4,%5,%6,%7}, {%8,%9}, {%0,%1,%2,%3};"
        : "+f"(d[0]), "+f"(d[1]), "+f"(d[2]), "+f"(d[3])
        : "r"(a[0]), "r"(a[1]), "r"(a[2]), "r"(a[3]), "r"(b0), "r"(b1));
}
__device__ __forceinline__ void split2(float f0, float f1,
                                       unsigned& hi, unsigned& lo) {
    __nv_bfloat16 h0 = __float2bfloat16_rn(f0);
    __nv_bfloat16 h1 = __float2bfloat16_rn(f1);
    hi = ((unsigned)__bfloat16_as_ushort(h1) << 16) |
          (unsigned)__bfloat16_as_ushort(h0);
    float l0 = f0 - __bfloat162float(h0);
    float l1 = f1 - __bfloat162float(h1);
    asm("cvt.rn.bf16x2.f32 %0, %1, %2;" : "=r"(lo) : "f"(l1), "f"(l0));
}

__global__ __launch_bounds__(256) void mma_gemm_kernel(
    const float* __restrict__ X, const float* __restrict__ Wl,
    const float* __restrict__ Wr, int N)
{
    extern __shared__ char smem[];
    unsigned sb = smem_u32(smem);
    const int tid    = threadIdx.x;
    const int lane   = tid & 31;
    const int wid    = tid >> 5;
    const int warp_m = wid >> 1;          // 0..3 -> rows warp_m*32
    const int warp_n = wid & 1;           // 0..1 -> cols warp_n*64 (per half)
    const int row0   = blockIdx.x * 128;

    // ---- fill A (split X rows) ----
    {
        int r = tid >> 1;
        int kb = (tid & 1) * 64;
        unsigned* ah = (unsigned*)(smem + OFF_AHI) + r * LDAU + (kb >> 1);
        unsigned* al = (unsigned*)(smem + OFF_ALO) + r * LDAU + (kb >> 1);
        int grow = row0 + r;
        if (grow < N) {
            const float4* xp = (const float4*)&X[(size_t)grow * F + kb];
            #pragma unroll
            for (int j = 0; j < 16; j++) {
                float4 v = __ldg(&xp[j]);
                unsigned h0, l0, h1, l1;
                split2(v.x, v.y, h0, l0);
                split2(v.z, v.w, h1, l1);
                ah[j * 2] = h0; ah[j * 2 + 1] = h1;
                al[j * 2] = l0; al[j * 2 + 1] = l1;
            }
        } else {
            #pragma unroll
            for (int j = 0; j < 32; j++) { ah[j] = 0u; al[j] = 0u; }
        }
    }
    // ---- fill B transposed (Bt[n][k] = W[k][n]), split ----
    {
        int n = tid;                       // 0..255
        const float* W = (n < 128) ? Wl : Wr;
        int nn = n & 127;
        unsigned* bh = (unsigned*)(smem + OFF_BHI) + n * LDAU;
        unsigned* bl = (unsigned*)(smem + OFF_BLO) + n * LDAU;
        #pragma unroll 8
        for (int k = 0; k < 128; k += 2) {
            float f0 = __ldg(&W[(size_t)k * 128 + nn]);
            float f1 = __ldg(&W[(size_t)(k + 1) * 128 + nn]);
            unsigned h, l;
            split2(f0, f1, h, l);
            bh[k >> 1] = h; bl[k >> 1] = l;
        }
    }
    __syncthreads();

    // per-lane ldmatrix address components (bytes)
    const unsigned aoff = (unsigned)(warp_m * 32 + (lane & 15)) * (LDA * 2) +
                          ((unsigned)(lane >> 4) << 4);
    const unsigned boff = (unsigned)((lane & 7) + ((lane >> 4) << 3)) * (LDA * 2) +
                          ((unsigned)((lane >> 3) & 1) << 4);

    #pragma unroll
    for (int h = 0; h < 2; h++) {
        float acc[2][8][4];
        #pragma unroll
        for (int mt = 0; mt < 2; mt++)
            #pragma unroll
            for (int nt = 0; nt < 8; nt++)
                #pragma unroll
                for (int q = 0; q < 4; q++) acc[mt][nt][q] = 0.f;

        const unsigned nbase = (unsigned)(h * 128 + warp_n * 64) * (LDA * 2);

        #pragma unroll
        for (int term = 0; term < 3; term++) {
            const unsigned Ab = sb + ((term < 2) ? OFF_AHI : OFF_ALO) + aoff;
            const unsigned Bb = sb + ((term == 1) ? OFF_BLO : OFF_BHI) + nbase + boff;
            #pragma unroll
            for (int ks = 0; ks < 8; ks++) {
                const unsigned kb = (unsigned)ks * 32;   // k0*2 bytes
                unsigned a0[4], a1[4];
                ldm4(a0, Ab + kb);
                ldm4(a1, Ab + 16 * (LDA * 2) + kb);
                unsigned b[4][4];
                #pragma unroll
                for (int p = 0; p < 4; p++)
                    ldm4(b[p], Bb + (unsigned)p * 16 * (LDA * 2) + kb);
                #pragma unroll
                for (int mt = 0; mt < 2; mt++) {
                    const unsigned* aa = mt ? a1 : a0;
                    #pragma unroll
                    for (int nt = 0; nt < 8; nt++)
                        mma16816(acc[mt][nt], aa,
                                 b[nt >> 1][(nt & 1) * 2],
                                 b[nt >> 1][(nt & 1) * 2 + 1]);
                }
            }
        }
        // store this half as fp16
        __half* dst = h ? g_xr_h : g_xl_h;
        #pragma unroll
        for (int mt = 0; mt < 2; mt++) {
            int row = row0 + warp_m * 32 + mt * 16 + (lane >> 2);
            #pragma unroll
            for (int nt = 0; nt < 8; nt++) {
                int col = warp_n * 64 + nt * 8 + (lane & 3) * 2;
                if (row < N)
                    *(__half2*)&dst[(size_t)row * HC + col] =
                        __floats2half2_rn(acc[mt][nt][0], acc[mt][nt][1]);
                if (row + 8 < N)
                    *(__half2*)&dst[(size_t)(row + 8) * HC + col] =
                        __floats2half2_rn(acc[mt][nt][2], acc[mt][nt][3]);
            }
        }
    }
}

// ---------------------------------------------------------------
// FUSED attention + column stats.  R7 structure: warp per dst node,
// lane owns 4 channels (head = lane>>3), shfl 4/2/1 score reduction.
// Change vs R7: 8-edge software pipeline (uint2 staging) + exp2.
__device__ __forceinline__ float4 cvt4h(uint2 u) {
    float2 f0 = __half22float2(*(__half2*)&u.x);
    float2 f1 = __half22float2(*(__half2*)&u.y);
    return make_float4(f0.x, f0.y, f1.x, f1.y);
}

__global__ __launch_bounds__(256) void fused_attn_kernel(
    const float* __restrict__ att, const float* __restrict__ bias,
    float* __restrict__ out, int N)
{
    __shared__ float bsum[HC];
    __shared__ float bssq[HC];
    const int tid = threadIdx.x;
    if (tid < HC) { bsum[tid] = 0.f; bssq[tid] = 0.f; }
    __syncthreads();

    const int node = blockIdx.x * 8 + (tid >> 5);
    if (node < N) {
        const int lane = tid & 31;
        const int c4 = lane * 4;

        // att pre-scaled by log2e -> bare exp2f per edge
        float4 a4 = *(const float4*)&att[c4];
        a4.x *= LOG2E; a4.y *= LOG2E; a4.z *= LOG2E; a4.w *= LOG2E;
        float4 r4 = cvt4h(*(const uint2*)&g_xr_h[(size_t)node * HC + c4]);

        float denom = 0.f;
        float4 acc = make_float4(0.f, 0.f, 0.f, 0.f);

#define EDGE_STEP(U) {                                               \
            float4 lv = cvt4h(U);                                    \
            float e0 = lv.x + r4.x; e0 = fmaxf(e0, NEG_SLOPE * e0);  \
            float e1 = lv.y + r4.y; e1 = fmaxf(e1, NEG_SLOPE * e1);  \
            float e2 = lv.z + r4.z; e2 = fmaxf(e2, NEG_SLOPE * e2);  \
            float e3 = lv.w + r4.w; e3 = fmaxf(e3, NEG_SLOPE * e3);  \
            float s = a4.x * e0 + a4.y * e1 + a4.z * e2 + a4.w * e3; \
            s += __shfl_xor_sync(0xffffffffu, s, 4);                 \
            s += __shfl_xor_sync(0xffffffffu, s, 2);                 \
            s += __shfl_xor_sync(0xffffffffu, s, 1);                 \
            float we = exp2f(s);                                     \
            denom += we;                                             \
            acc.x = fmaf(we, lv.x, acc.x);                           \
            acc.y = fmaf(we, lv.y, acc.y);                           \
            acc.z = fmaf(we, lv.z, acc.z);                           \
            acc.w = fmaf(we, lv.w, acc.w); }

        // self loop
        EDGE_STEP(*(const uint2*)&g_xl_h[(size_t)node * HC + c4]);

        const int cnt = min(g_count[node], ELL_CAP);
        const int* lst = &g_ell[(size_t)node * ELL_CAP];

        int i = 0;
        // 8-edge pipelined main loop: 2 int4 index loads + 8 gathers in flight
        for (; i + 8 <= cnt; i += 8) {
            int4 sa = *(const int4*)&lst[i];
            int4 sb = *(const int4*)&lst[i + 4];
            uint2 u0 = *(const uint2*)&g_xl_h[(size_t)sa.x * HC + c4];
            uint2 u1 = *(const uint2*)&g_xl_h[(size_t)sa.y * HC + c4];
            uint2 u2 = *(const uint2*)&g_xl_h[(size_t)sa.z * HC + c4];
            uint2 u3 = *(const uint2*)&g_xl_h[(size_t)sa.w * HC + c4];
            uint2 u4 = *(const uint2*)&g_xl_h[(size_t)sb.x * HC + c4];
            uint2 u5 = *(const uint2*)&g_xl_h[(size_t)sb.y * HC + c4];
            uint2 u6 = *(const uint2*)&g_xl_h[(size_t)sb.z * HC + c4];
            uint2 u7 = *(const uint2*)&g_xl_h[(size_t)sb.w * HC + c4];
            EDGE_STEP(u0); EDGE_STEP(u1); EDGE_STEP(u2); EDGE_STEP(u3);
            EDGE_STEP(u4); EDGE_STEP(u5); EDGE_STEP(u6); EDGE_STEP(u7);
        }
        for (; i + 4 <= cnt; i += 4) {
            int4 sa = *(const int4*)&lst[i];
            uint2 u0 = *(const uint2*)&g_xl_h[(size_t)sa.x * HC + c4];
            uint2 u1 = *(const uint2*)&g_xl_h[(size_t)sa.y * HC + c4];
            uint2 u2 = *(const uint2*)&g_xl_h[(size_t)sa.z * HC + c4];
            uint2 u3 = *(const uint2*)&g_xl_h[(size_t)sa.w * HC + c4];
            EDGE_STEP(u0); EDGE_STEP(u1); EDGE_STEP(u2); EDGE_STEP(u3);
        }
        for (; i < cnt; i++) {
            int s = __ldg(&lst[i]);
            EDGE_STEP(*(const uint2*)&g_xl_h[(size_t)s * HC + c4]);
        }
#undef EDGE_STEP

        float inv = 1.f / denom;
        float4 b4 = *(const float4*)&bias[c4];
        float4 o = make_float4(
            fmaf(acc.x, inv, b4.x), fmaf(acc.y, inv, b4.y),
            fmaf(acc.z, inv, b4.z), fmaf(acc.w, inv, b4.w));
        *(float4*)&out[(size_t)node * HC + c4] = o;
        atomicAdd(&bsum[c4 + 0], o.x); atomicAdd(&bssq[c4 + 0], o.x * o.x);
        atomicAdd(&bsum[c4 + 1], o.y); atomicAdd(&bssq[c4 + 1], o.y * o.y);
        atomicAdd(&bsum[c4 + 2], o.z); atomicAdd(&bssq[c4 + 2], o.z * o.z);
        atomicAdd(&bsum[c4 + 3], o.w); atomicAdd(&bssq[c4 + 3], o.w * o.w);
    }
    __syncthreads();
    if (tid < HC) {
        atomicAdd(&g_colsum[tid], bsum[tid]);
        atomicAdd(&g_colsumsq[tid], bssq[tid]);
    }
}

// ---------------------------------------------------------------
__global__ void norm_kernel(float* __restrict__ out,
                            const float* __restrict__ gw,
                            const float* __restrict__ gb,
                            const float* __restrict__ gms, int N)
{
    int i = blockIdx.x * blockDim.x + threadIdx.x;
    if (i >= N * HC) return;
    int f = i & (HC - 1);
    float invN = 1.f / (float)N;
    float m  = g_colsum[f] * invN;
    float m2 = g_colsumsq[f] * invN;
    float s  = gms[f];
    float var = m2 - s * (2.f - s) * m * m;
    float v = out[i];
    out[i] = gw[f] * (v - s * m) * rsqrtf(var + GN_EPS) + gb[f];
}

// ---------------------------------------------------------------
extern "C" void kernel_launch(void* const* d_in, const int* in_sizes, int n_in,
                              void* d_out, int out_size)
{
    const float* x    = (const float*)d_in[0];
    const int*   ei   = (const int*)  d_in[1];
    const float* W_l  = (const float*)d_in[2];
    const float* W_r  = (const float*)d_in[3];
    const float* att  = (const float*)d_in[4];
    const float* bias = (const float*)d_in[5];
    const float* gw   = (const float*)d_in[6];
    const float* gb   = (const float*)d_in[7];
    const float* gms  = (const float*)d_in[8];
    float* out = (float*)d_out;

    const int N = in_sizes[0] / F;
    const int E = in_sizes[1] / 2;

    static int smem_set = 0;
    if (!smem_set) {
        cudaFuncSetAttribute(mma_gemm_kernel,
                             cudaFuncAttributeMaxDynamicSharedMemorySize, SM_TOT);
        smem_set = 1;
    }

    // adjacency (ELL) build
    init_kernel<<<(N + 255) / 256, 256>>>(N);
    ell_kernel<<<(E + 255) / 256, 256>>>(ei, E);

    // projections (tensor-core, split-bf16, both outputs in one pass)
    mma_gemm_kernel<<<(N + 127) / 128, 256, SM_TOT>>>(x, W_l, W_r, N);

    // fused attention (softmax + aggregation + column stats)
    fused_attn_kernel<<<(N + 7) / 8, 256>>>(att, bias, out, N);

    // GraphNorm
    norm_kernel<<<(N * HC + 255) / 256, 256>>>(out, gw, gb, gms, N);
}